// round 8
// baseline (speedup 1.0000x reference)
#include <cuda_runtime.h>

#define FULLMASK 0xffffffffu

typedef unsigned long long u64;
struct alignas(8) C2 { float x, y; };

__device__ __forceinline__ C2 cmul(C2 a, C2 b){
    C2 r; r.x = a.x*b.x - a.y*b.y; r.y = a.x*b.y + a.y*b.x; return r;
}

// ── packed f32x2 primitives (state stays packed in b64 regs) ──
__device__ __forceinline__ u64 pk(float x, float y){
    u64 r; asm("mov.b64 %0, {%1,%2};" : "=l"(r) : "f"(x), "f"(y)); return r;
}
__device__ __forceinline__ void upk(u64 v, float& x, float& y){
    asm("mov.b64 {%0,%1}, %2;" : "=f"(x), "=f"(y) : "l"(v));
}
__device__ __forceinline__ u64 swp(u64 v){ float x,y; upk(v,x,y); return pk(y,x); }
__device__ __forceinline__ u64 pmul(u64 a, u64 b){
    u64 d; asm("mul.rn.f32x2 %0, %1, %2;" : "=l"(d) : "l"(a), "l"(b)); return d;
}
__device__ __forceinline__ u64 pfma(u64 a, u64 b, u64 c){
    u64 d; asm("fma.rn.f32x2 %0, %1, %2, %3;" : "=l"(d) : "l"(a), "l"(b), "l"(c)); return d;
}
__device__ __forceinline__ u64 shfl64(u64 v, int m){
    float x,y; upk(v,x,y);
    x = __shfl_xor_sync(FULLMASK, x, m);
    y = __shfl_xor_sync(FULLMASK, y, m);
    return pk(x,y);
}
__device__ __forceinline__ u64 shfl64s(u64 v, int m){ // shuffled + swapped (swap folds into repack)
    float x,y; upk(v,x,y);
    x = __shfl_xor_sync(FULLMASK, x, m);
    y = __shfl_xor_sync(FULLMASK, y, m);
    return pk(y,x);
}

// st[j] = vc (.) st[j] + vs (.) partner ; partner = st[j^TM] at lane^TL (opt swapped)
template<int TL, int TM, int CM, bool SWAP>
__device__ __forceinline__ void cr_packed(u64 st[8], u64 vc, u64 vs){
    u64 p[8];
#pragma unroll
    for (int j = 0; j < 8; j++) if (CM == 0 || (j & CM)){
        u64 v = st[j ^ TM];
        if (TL) p[j] = SWAP ? shfl64s(v, TL) : shfl64(v, TL);
        else    p[j] = SWAP ? swp(v) : v;
    }
#pragma unroll
    for (int j = 0; j < 8; j++) if (CM == 0 || (j & CM))
        st[j] = pfma(vc, st[j], pmul(vs, p[j]));
}

// same, reading src, writing st (folds branch base copy into gate 0)
template<int TL, int TM, bool SWAP>
__device__ __forceinline__ void cr_packed_g(const u64 src[8], u64 st[8], u64 vc, u64 vs){
    u64 p[8];
#pragma unroll
    for (int j = 0; j < 8; j++){
        u64 v = src[j ^ TM];
        if (TL) p[j] = SWAP ? shfl64s(v, TL) : shfl64(v, TL);
        else    p[j] = SWAP ? swp(v) : v;
    }
#pragma unroll
    for (int j = 0; j < 8; j++) st[j] = pfma(vc, src[j], pmul(vs, p[j]));
}

// CRY on a register-target bit: sign of vs by j&TM (compile time), no swaps at all
template<int TM, int CM>
__device__ __forceinline__ void cry_reg(u64 st[8], u64 vc, u64 vsp, u64 vsm){
    u64 p[8];
#pragma unroll
    for (int j = 0; j < 8; j++) if (CM == 0 || (j & CM)) p[j] = st[j ^ TM];
#pragma unroll
    for (int j = 0; j < 8; j++) if (CM == 0 || (j & CM))
        st[j] = pfma(vc, st[j], pmul((j & TM) ? vsp : vsm, p[j]));
}

// U3 full complex 2x2, packed: d = va(.)s + vb(.)s~ + vcc(.)p + ve(.)p~
template<int TL, int TM>
__device__ __forceinline__ void u3_gate(u64 st[8], int lane, const C2* m){
    float4 q0 = *(const float4*)(m);      // m00r, 0, m01.x, m01.y
    float4 q1 = *(const float4*)(m + 2);  // m10.x, m10.y, m11.x, m11.y
    if constexpr (TL != 0){
        bool tb = (lane & TL) != 0;
        float ax = tb ? q1.z : q0.x;
        float ay = tb ? q1.w : 0.f;
        float bx = tb ? q1.x : q0.z;
        float by = tb ? q1.y : q0.w;
        u64 va = pk(ax,ax), vb = pk(-ay,ay), vcc = pk(bx,bx), ve = pk(-by,by);
        u64 p[8], ps[8];
#pragma unroll
        for (int j = 0; j < 8; j++){
            float x,y; upk(st[j], x, y);
            x = __shfl_xor_sync(FULLMASK, x, TL);
            y = __shfl_xor_sync(FULLMASK, y, TL);
            p[j] = pk(x,y); ps[j] = pk(y,x);
        }
#pragma unroll
        for (int j = 0; j < 8; j++){
            u64 d = pmul(va, st[j]);
            d = pfma(vb, swp(st[j]), d);
            d = pfma(vcc, p[j], d);
            d = pfma(ve, ps[j], d);
            st[j] = d;
        }
    } else {
        u64 va1 = pk(q1.z,q1.z), vb1 = pk(-q1.w,q1.w), vc1 = pk(q1.x,q1.x), ve1 = pk(-q1.y,q1.y);
        u64 va0 = pk(q0.x,q0.x), vc0 = pk(q0.z,q0.z), ve0 = pk(-q0.w,q0.w);
        u64 p[8];
#pragma unroll
        for (int j = 0; j < 8; j++) p[j] = st[j ^ TM];
#pragma unroll
        for (int j = 0; j < 8; j++){
            u64 d;
            if (j & TM){
                d = pmul(va1, st[j]);
                d = pfma(vb1, swp(st[j]), d);
                d = pfma(vc1, p[j], d);
                d = pfma(ve1, swp(p[j]), d);
            } else {
                d = pmul(va0, st[j]);
                d = pfma(vc0, p[j], d);
                d = pfma(ve0, swp(p[j]), d);
            }
            st[j] = d;
        }
    }
}

// Z3 -> reg bit 2, Z7 -> reg bit 1 (post-remap)
__device__ __forceinline__ void measure(const u64 st[8], float& z3, float& z7){
    float a3 = 0.f, a7 = 0.f;
#pragma unroll
    for (int j = 0; j < 8; j++){
        float x,y; upk(st[j], x, y);
        float pr = x*x + y*y;
        a3 += (j & 2) ? -pr : pr;
        a7 += (j & 1) ? -pr : pr;
    }
#pragma unroll
    for (int o = 16; o; o >>= 1){
        a3 += __shfl_xor_sync(FULLMASK, a3, o);
        a7 += __shfl_xor_sync(FULLMASK, a7, o);
    }
    z3 = a3; z7 = a7;
}

// ── Branch-phase wire map (after w3<->w6 swap) ──
//  lanes: w0:16  w1:8  w2:4  w6:2  w4:1     regs: w5:4  w3:2  w7:1
__device__ __forceinline__ void run_branch_x(const u64 base[8], int lane,
        const float* crc, const float* crs, const C2* u3m, float& z3, float& z7){
    u64 st[8];
#define CRXC(CLBIT, i) \
        float cc, ss; \
        if (CLBIT){ bool ct = (lane & (CLBIT)) != 0; cc = ct ? crc[i] : 1.f; ss = ct ? crs[i] : 0.f; } \
        else { cc = crc[i]; ss = crs[i]; } \
        u64 vc = pk(cc,cc), vs = pk(ss,-ss);
    { CRXC(16, 0) cr_packed_g<8,0,true>(base, st, vc, vs); }   // (0,1)
#define CRXG(TL,TM,CM, CLBIT, i) { CRXC(CLBIT, i) cr_packed<TL,TM,CM,true>(st, vc, vs); }
    CRXG(0,2,0,  4, 1)   // (2,3)
    CRXG(0,4,0,  1, 2)   // (4,5)
    CRXG(0,1,0,  2, 3)   // (6,7)
    CRXG(4,0,0,  8, 4)   // (1,2)
    CRXG(1,0,2,  0, 5)   // (3,4)
    CRXG(2,0,4,  0, 6)   // (5,6)
    u3_gate<8,0>(st, lane, u3m + 0*4);
    u3_gate<0,2>(st, lane, u3m + 1*4);
    u3_gate<0,4>(st, lane, u3m + 2*4);
    u3_gate<0,1>(st, lane, u3m + 3*4);
    CRXG(0,2,0,  8, 7)   // (1,3)
    CRXG(0,1,4,  0, 8)   // (5,7)
    CRXG(0,4,2,  0, 9)   // (3,5)
#undef CRXG
#undef CRXC
    u3_gate<0,2>(st, lane, u3m + 4*4);
    u3_gate<0,1>(st, lane, u3m + 5*4);
    measure(st, z3, z7);
}

__device__ __forceinline__ void run_branch_y(const u64 base[8], int lane,
        const float* crc, const float* crs, const C2* u3m, float& z3, float& z7){
    u64 st[8];
    {   // (0,1): lane target 8, ctrl lane16, read from base
        float sel = (lane & 8) ? crs[0] : -crs[0];
        bool ct = (lane & 16) != 0;
        float cc = ct ? crc[0] : 1.f;
        float ss = ct ? sel : 0.f;
        cr_packed_g<8,0,false>(base, st, pk(cc,cc), pk(ss,ss));
    }
#define CRYL(TL,CM, CLBIT, i) { \
        float cc, ss; \
        float sel = (lane & (TL)) ? crs[i] : -crs[i]; \
        if (CLBIT){ bool ct = (lane & (CLBIT)) != 0; cc = ct ? crc[i] : 1.f; ss = ct ? sel : 0.f; } \
        else { cc = crc[i]; ss = sel; } \
        cr_packed<TL,0,CM,false>(st, pk(cc,cc), pk(ss,ss)); }
#define CRYR(TM,CM, CLBIT, i) { \
        float cc, ssp; \
        if (CLBIT){ bool ct = (lane & (CLBIT)) != 0; cc = ct ? crc[i] : 1.f; ssp = ct ? crs[i] : 0.f; } \
        else { cc = crc[i]; ssp = crs[i]; } \
        cry_reg<TM,CM>(st, pk(cc,cc), pk(ssp,ssp), pk(-ssp,-ssp)); }
    CRYR(2,0,  4, 1)   // (2,3)
    CRYR(4,0,  1, 2)   // (4,5)
    CRYR(1,0,  2, 3)   // (6,7)
    CRYL(4,0,  8, 4)   // (1,2)
    CRYL(1,2,  0, 5)   // (3,4)
    CRYL(2,4,  0, 6)   // (5,6)
    u3_gate<8,0>(st, lane, u3m + 0*4);
    u3_gate<0,2>(st, lane, u3m + 1*4);
    u3_gate<0,4>(st, lane, u3m + 2*4);
    u3_gate<0,1>(st, lane, u3m + 3*4);
    CRYR(2,0,  8, 7)   // (1,3)
    CRYR(1,4,  0, 8)   // (5,7)
    CRYR(4,2,  0, 9)   // (3,5)
#undef CRYL
#undef CRYR
    u3_gate<0,2>(st, lane, u3m + 4*4);
    u3_gate<0,1>(st, lane, u3m + 5*4);
    measure(st, z3, z7);
}

// CRZ branch: diagonal layers via pre-packed phase tables (LDS.64 + 2 packed ops)
__device__ __forceinline__ void run_branch_z(const u64 base[8], int lane,
        const u64* pAc, const u64* pAs, const u64* pBc, const u64* pBs,
        const C2* u3m, float& z3, float& z7){
    u64 st[8];
#pragma unroll
    for (int j = 0; j < 8; j++)
        st[j] = pfma(pAc[j*32 + lane], base[j], pmul(pAs[j*32 + lane], swp(base[j])));
    u3_gate<8,0>(st, lane, u3m + 0*4);
    u3_gate<0,2>(st, lane, u3m + 1*4);
    u3_gate<0,4>(st, lane, u3m + 2*4);
    u3_gate<0,1>(st, lane, u3m + 3*4);
#pragma unroll
    for (int j = 0; j < 8; j++)
        st[j] = pfma(pBc[j*32 + lane], st[j], pmul(pBs[j*32 + lane], swp(st[j])));
    u3_gate<0,2>(st, lane, u3m + 4*4);
    u3_gate<0,1>(st, lane, u3m + 5*4);
    measure(st, z3, z7);
}

__global__ void __launch_bounds__(128, 5)
qcnn_kernel(const float* __restrict__ theta, const float* __restrict__ phi,
            const float* __restrict__ crw, const float* __restrict__ u3p,
            const float* __restrict__ W1, const float* __restrict__ b1,
            const float* __restrict__ W2, const float* __restrict__ b2,
            float* __restrict__ out, int n)
{
    __shared__ float s_crc[10], s_crs[10];
    __shared__ C2 s_u3[18*4];             // per gate: {m00r,0},{m01},{m10},{m11}
    __shared__ float s_W1[72], s_b1[12], s_W2[12], s_b2;
    __shared__ u64 s_pAc[256], s_pAs[256], s_pBc[256], s_pBs[256]; // packed CRZ phases

    int tid = threadIdx.x;
    if (tid < 72)                         s_W1[tid]     = W1[tid];
    else if (tid < 84)                    s_b1[tid-72]  = b1[tid-72];
    else if (tid < 96)                    s_W2[tid-84]  = W2[tid-84];
    else if (tid == 96)                   s_b2          = b2[0];
    else if (tid >= 98 && tid < 108){
        int i = tid - 98;
        float t = 0.5f * crw[i];
        s_crc[i] = cosf(t);
        s_crs[i] = sinf(t);
    } else if (tid >= 108 && tid < 126){
        int g = tid - 108;   // branch*6 + gate
        float t  = u3p[g*3+0], ph = u3p[g*3+1], la = u3p[g*3+2];
        float ct, stt; sincosf(0.5f*t, &stt, &ct);
        float cl, sl;  sincosf(la,     &sl,  &cl);
        float cp, sp;  sincosf(ph,     &sp,  &cp);
        s_u3[g*4+0] = C2{ct, 0.f};
        s_u3[g*4+1] = C2{-cl*stt, -sl*stt};
        s_u3[g*4+2] = C2{cp*stt,  sp*stt};
        s_u3[g*4+3] = C2{(cp*cl - sp*sl)*ct, (cp*sl + sp*cl)*ct};
    }
    __syncthreads();

    // CRZ phase tables (pre-packed). Wire w bit of a = (a >> (7-w)) & 1.
    // Post-remap: lane = w0<<4|w1<<3|w2<<2|w6<<1|w4 ; j = w5<<2|w3<<1|w7
#pragma unroll
    for (int a = tid; a < 256; a += 128){
        C2 pA{1.f, 0.f}, pB{1.f, 0.f};
#define CRZF(P, cw, tw, i) \
        if ((a >> (7-(cw))) & 1){ \
            float ss = ((a >> (7-(tw))) & 1) ? s_crs[i] : -s_crs[i]; \
            P = cmul(P, C2{s_crc[i], ss}); \
        }
        CRZF(pA, 0,1, 0) CRZF(pA, 2,3, 1) CRZF(pA, 4,5, 2) CRZF(pA, 6,7, 3)
        CRZF(pA, 1,2, 4) CRZF(pA, 3,4, 5) CRZF(pA, 5,6, 6)
        CRZF(pB, 1,3, 7) CRZF(pB, 5,7, 8) CRZF(pB, 3,5, 9)
#undef CRZF
        int w0=(a>>7)&1, w1=(a>>6)&1, w2=(a>>5)&1, w3=(a>>4)&1;
        int w4=(a>>3)&1, w5=(a>>2)&1, w6=(a>>1)&1, w7=a&1;
        int idx = ((w5<<2)|(w3<<1)|w7)*32 + ((w0<<4)|(w1<<3)|(w2<<2)|(w6<<1)|w4);
        s_pAc[idx] = pk(pA.x, pA.x);
        s_pAs[idx] = pk(-pA.y, pA.y);
        s_pBc[idx] = pk(pB.x, pB.x);
        s_pBs[idx] = pk(-pB.y, pB.y);
    }
    __syncthreads();

    int lane = tid & 31;
    int sample = blockIdx.x * 4 + (tid >> 5);
    if (sample >= n) return;

    float th = theta[sample], fi = phi[sample];
    float cth, sth; __sincosf(th, &sth, &cth);
    u64 vrc = pk(cth, cth), vrs = pk(sth, -sth);

    // RZ layer = diag phase e^{i*phi*(2*popc(a)-8)} (loop map: w0-4 lanes, w5-7 regs)
    C2 z; __sincosf(2.f*fi, &z.y, &z.x);
    int pcl = __popc(lane);
    C2 wk[4];
    __sincosf(2.f*fi*(float)(pcl - 4), &wk[0].y, &wk[0].x);
    wk[1] = cmul(wk[0], z);
    wk[2] = cmul(wk[1], z);
    wk[3] = cmul(wk[2], z);
    u64 wxp[4], wyp[4];
#pragma unroll
    for (int k = 0; k < 4; k++){ wxp[k] = pk(wk[k].x, wk[k].x); wyp[k] = pk(-wk[k].y, wk[k].y); }

    u64 st[8];
#pragma unroll
    for (int j = 0; j < 8; j++) st[j] = pk(0.0625f, 0.f);

    const int pcj[8] = {0,1,1,2,1,2,2,3};
#pragma unroll 1
    for (int cyc = 0; cyc < 4; cyc++){
#pragma unroll
        for (int j = 0; j < 8; j++)
            st[j] = pfma(wxp[pcj[j]], st[j], pmul(wyp[pcj[j]], swp(st[j])));
        // Loop map: w0:16 w1:8 w2:4 w3:2 w4:1 | w5:4 w6:2 w7:1
        cr_packed<24,0,0,true>(st, vrc, vrs);  // (0,1)
        cr_packed< 6,0,0,true>(st, vrc, vrs);  // (2,3)
        cr_packed< 1,4,0,true>(st, vrc, vrs);  // (4,5)
        cr_packed< 0,3,0,true>(st, vrc, vrs);  // (6,7)
        cr_packed<12,0,0,true>(st, vrc, vrs);  // (1,2)
        cr_packed< 3,0,0,true>(st, vrc, vrs);  // (3,4)
        cr_packed< 0,6,0,true>(st, vrc, vrs);  // (5,6)
    }

    // Remap: swap wire 3 (lane bit 2) <-> wire 6 (reg bit 2).
#pragma unroll
    for (int j0i = 0; j0i < 4; j0i++){
        const int j0 = (j0i & 1) | ((j0i & 2) << 1);  // {0,1,4,5}
        const int jh = j0 | 2;
        bool hi = (lane & 2) != 0;
        u64 send = hi ? st[j0] : st[jh];
        send = shfl64(send, 2);
        if (hi) st[j0] = send; else st[jh] = send;
    }

    float feat[6];
    run_branch_x(st, lane, s_crc, s_crs, s_u3 + 0,   feat[0], feat[1]);
    run_branch_y(st, lane, s_crc, s_crs, s_u3 + 24,  feat[2], feat[3]);
    run_branch_z(st, lane, s_pAc, s_pAs, s_pBc, s_pBs, s_u3 + 48, feat[4], feat[5]);

    if (lane == 0){
        float acc = s_b2;
#pragma unroll
        for (int k = 0; k < 12; k++){
            float u = s_b1[k];
#pragma unroll
            for (int i = 0; i < 6; i++) u += s_W1[k*6+i] * feat[i];
            float e = __expf(2.f*u);                 // tanh via exp
            acc += s_W2[k] * (1.f - __fdividef(2.f, e + 1.f));
        }
        out[sample] = __fdividef(1.f, 1.f + __expf(-acc));
    }
}

extern "C" void kernel_launch(void* const* d_in, const int* in_sizes, int n_in,
                              void* d_out, int out_size)
{
    const float* theta = (const float*)d_in[0];
    const float* phi   = (const float*)d_in[1];
    const float* crw   = (const float*)d_in[2];
    const float* u3p   = (const float*)d_in[3];
    const float* W1    = (const float*)d_in[4];
    const float* b1    = (const float*)d_in[5];
    const float* W2    = (const float*)d_in[6];
    const float* b2    = (const float*)d_in[7];
    float* out = (float*)d_out;
    int n = in_sizes[0];
    int blocks = (n + 3) / 4;
    qcnn_kernel<<<blocks, 128>>>(theta, phi, crw, u3p, W1, b1, W2, b2, out, n);
}

// round 12
// speedup vs baseline: 1.0207x; 1.0207x over previous
#include <cuda_runtime.h>

#define FULLMASK 0xffffffffu

typedef unsigned long long u64;
struct C2 { float x, y; };

__device__ __forceinline__ C2 cmul(C2 a, C2 b){
    C2 r; r.x = a.x*b.x - a.y*b.y; r.y = a.x*b.y + a.y*b.x; return r;
}

// ── packed f32x2 primitives; a u64 holds {sample0, sample1} of ONE real plane ──
__device__ __forceinline__ u64 pk(float x, float y){
    u64 r; asm("mov.b64 %0, {%1,%2};" : "=l"(r) : "f"(x), "f"(y)); return r;
}
__device__ __forceinline__ void upk(u64 v, float& x, float& y){
    asm("mov.b64 {%0,%1}, %2;" : "=f"(x), "=f"(y) : "l"(v));
}
__device__ __forceinline__ u64 pmul(u64 a, u64 b){
    u64 d; asm("mul.rn.f32x2 %0, %1, %2;" : "=l"(d) : "l"(a), "l"(b)); return d;
}
__device__ __forceinline__ u64 pfma(u64 a, u64 b, u64 c){
    u64 d; asm("fma.rn.f32x2 %0, %1, %2, %3;" : "=l"(d) : "l"(a), "l"(b), "l"(c)); return d;
}
__device__ __forceinline__ u64 padd(u64 a, u64 b){
    u64 d; asm("add.rn.f32x2 %0, %1, %2;" : "=l"(d) : "l"(a), "l"(b)); return d;
}
__device__ __forceinline__ u64 shfl64(u64 v, int m){
    float x,y; upk(v,x,y);
    x = __shfl_xor_sync(FULLMASK, x, m);
    y = __shfl_xor_sync(FULLMASK, y, m);
    return pk(x,y);
}

// partner planes: p[j] = plane[j^TM] at lane^TL
template<int TL, int TM, int CM>
__device__ __forceinline__ void fetchp(const u64 re[8], const u64 im[8],
                                       u64 pre[8], u64 pim[8]){
#pragma unroll
    for (int j = 0; j < 8; j++) if (CM == 0 || (j & CM)){
        u64 a = re[j ^ TM], b = im[j ^ TM];
        if (TL){ a = shfl64(a, TL); b = shfl64(b, TL); }
        pre[j] = a; pim[j] = b;
    }
}

// CRX-form (RXX same): new = c*old - i*s*p  ->  re' = vc.re + vs.p_im ; im' = vc.im + vsn.p_re
// src/dst may alias.
template<int TL, int TM, int CM>
__device__ __forceinline__ void crx_g(const u64 sre[8], const u64 sim[8],
                                      u64 re[8], u64 im[8], u64 vc, u64 vs, u64 vsn){
    u64 pre[8], pim[8]; fetchp<TL,TM,CM>(sre, sim, pre, pim);
#pragma unroll
    for (int j = 0; j < 8; j++) if (CM == 0 || (j & CM)){
        u64 r = pfma(vc, sre[j], pmul(vs, pim[j]));
        im[j] = pfma(vc, sim[j], pmul(vsn, pre[j]));
        re[j] = r;
    }
}

// CRY-form: new = c*old +/- s*p (same sign both planes); TL-target: sign folded (vsp==vsm)
template<int TL, int TM, int CM>
__device__ __forceinline__ void cry_g(const u64 sre[8], const u64 sim[8],
                                      u64 re[8], u64 im[8], u64 vc, u64 vsp, u64 vsm){
    u64 pre[8], pim[8]; fetchp<TL,TM,CM>(sre, sim, pre, pim);
#pragma unroll
    for (int j = 0; j < 8; j++) if (CM == 0 || (j & CM)){
        u64 sel = (TM && (j & TM)) ? vsp : (TM ? vsm : vsp);
        re[j] = pfma(vc, sre[j], pmul(sel, pre[j]));
        im[j] = pfma(vc, sim[j], pmul(sel, pim[j]));
    }
}

// U3 full complex 2x2 from pre-packed shared table (12 u64 per gate):
// [0..5]=tb0: Ar,Ai,Ain,Br,Bi,Bin (A=m00 real, B=m01); [6..11]=tb1 (A=m11, B=m10)
template<int TL, int TM>
__device__ __forceinline__ void u3_g(u64 re[8], u64 im[8], int lane, const u64* gp){
    u64 pre[8], pim[8]; fetchp<TL,TM,0>(re, im, pre, pim);
    if constexpr (TL != 0){
        const u64* q = gp + ((lane & TL) ? 6 : 0);
        u64 Ar=q[0], Ai=q[1], Ain=q[2], Br=q[3], Bi=q[4], Bin=q[5];
#pragma unroll
        for (int j = 0; j < 8; j++){
            u64 r = pfma(Ar, re[j], pfma(Ain, im[j], pfma(Br, pre[j], pmul(Bin, pim[j]))));
            im[j] = pfma(Ar, im[j], pfma(Ai,  re[j], pfma(Br, pim[j], pmul(Bi,  pre[j]))));
            re[j] = r;
        }
    } else {
        u64 A0 = gp[0], B0r = gp[3], B0i = gp[4], B0in = gp[5];
        u64 A1r = gp[6], A1i = gp[7], A1in = gp[8], B1r = gp[9], B1i = gp[10], B1in = gp[11];
#pragma unroll
        for (int j = 0; j < 8; j++){
            u64 r, i2;
            if (j & TM){
                r  = pfma(A1r, re[j], pfma(A1in, im[j], pfma(B1r, pre[j], pmul(B1in, pim[j]))));
                i2 = pfma(A1r, im[j], pfma(A1i,  re[j], pfma(B1r, pim[j], pmul(B1i,  pre[j]))));
            } else {
                r  = pfma(A0, re[j], pfma(B0r, pre[j], pmul(B0in, pim[j])));
                i2 = pfma(A0, im[j], pfma(B0r, pim[j], pmul(B0i,  pre[j])));
            }
            re[j] = r; im[j] = i2;
        }
    }
}

// Z3 -> reg bit 2, Z7 -> reg bit 1 (post-remap). Packed over the sample pair.
__device__ __forceinline__ void measure(const u64 re[8], const u64 im[8],
                                        u64 pm1, u64& z3, u64& z7){
    u64 a3 = 0ull, a7 = 0ull;
#pragma unroll
    for (int j = 0; j < 8; j++){
        u64 pp = pfma(im[j], im[j], pmul(re[j], re[j]));
        a3 = (j & 2) ? pfma(pp, pm1, a3) : padd(a3, pp);
        a7 = (j & 1) ? pfma(pp, pm1, a7) : padd(a7, pp);
    }
#pragma unroll
    for (int o = 16; o; o >>= 1){
        a3 = padd(a3, shfl64(a3, o));
        a7 = padd(a7, shfl64(a7, o));
    }
    z3 = a3; z7 = a7;
}

// ── Branch-phase wire map (after w3<->w6 swap) ──
//  lanes: w0:16  w1:8  w2:4  w6:2  w4:1     regs: w5:4  w3:2  w7:1
__device__ __forceinline__ void run_branch_x(const u64 bre[8], const u64 bim[8], int lane,
        const float* crc, const float* crs, const u64* u3p, u64 pm1, u64& z3, u64& z7){
    u64 re[8], im[8];
#define CRXC(CLBIT, i) \
        float cc, ss; \
        if (CLBIT){ bool ct = (lane & (CLBIT)) != 0; cc = ct ? crc[i] : 1.f; ss = ct ? crs[i] : 0.f; } \
        else { cc = crc[i]; ss = crs[i]; } \
        u64 vc = pk(cc,cc), vs = pk(ss,ss), vsn = pk(-ss,-ss);
    { CRXC(16, 0) crx_g<8,0,0>(bre, bim, re, im, vc, vs, vsn); }   // (0,1)
#define CRXG(TL,TM,CM, CLBIT, i) { CRXC(CLBIT, i) crx_g<TL,TM,CM>(re, im, re, im, vc, vs, vsn); }
    CRXG(0,2,0,  4, 1)   // (2,3)
    CRXG(0,4,0,  1, 2)   // (4,5)
    CRXG(0,1,0,  2, 3)   // (6,7)
    CRXG(4,0,0,  8, 4)   // (1,2)
    CRXG(1,0,2,  0, 5)   // (3,4)
    CRXG(2,0,4,  0, 6)   // (5,6)
    u3_g<8,0>(re, im, lane, u3p + 0*12);
    u3_g<0,2>(re, im, lane, u3p + 1*12);
    u3_g<0,4>(re, im, lane, u3p + 2*12);
    u3_g<0,1>(re, im, lane, u3p + 3*12);
    CRXG(0,2,0,  8, 7)   // (1,3)
    CRXG(0,1,4,  0, 8)   // (5,7)
    CRXG(0,4,2,  0, 9)   // (3,5)
#undef CRXG
#undef CRXC
    u3_g<0,2>(re, im, lane, u3p + 4*12);
    u3_g<0,1>(re, im, lane, u3p + 5*12);
    measure(re, im, pm1, z3, z7);
}

__device__ __forceinline__ void run_branch_y(const u64 bre[8], const u64 bim[8], int lane,
        const float* crc, const float* crs, const u64* u3p, u64 pm1, u64& z3, u64& z7){
    u64 re[8], im[8];
    {   // (0,1): lane target 8, ctrl lane16
        float sel = (lane & 8) ? crs[0] : -crs[0];
        bool ct = (lane & 16) != 0;
        float cc = ct ? crc[0] : 1.f;
        float ss = ct ? sel : 0.f;
        u64 vc = pk(cc,cc), vv = pk(ss,ss);
        cry_g<8,0,0>(bre, bim, re, im, vc, vv, vv);
    }
#define CRYL(TL,CM, CLBIT, i) { \
        float cc, ss; \
        float sel = (lane & (TL)) ? crs[i] : -crs[i]; \
        if (CLBIT){ bool ct = (lane & (CLBIT)) != 0; cc = ct ? crc[i] : 1.f; ss = ct ? sel : 0.f; } \
        else { cc = crc[i]; ss = sel; } \
        u64 vc = pk(cc,cc), vv = pk(ss,ss); \
        cry_g<TL,0,CM>(re, im, re, im, vc, vv, vv); }
#define CRYR(TM,CM, CLBIT, i) { \
        float cc, ssp; \
        if (CLBIT){ bool ct = (lane & (CLBIT)) != 0; cc = ct ? crc[i] : 1.f; ssp = ct ? crs[i] : 0.f; } \
        else { cc = crc[i]; ssp = crs[i]; } \
        cry_g<0,TM,CM>(re, im, re, im, pk(cc,cc), pk(ssp,ssp), pk(-ssp,-ssp)); }
    CRYR(2,0,  4, 1)   // (2,3)
    CRYR(4,0,  1, 2)   // (4,5)
    CRYR(1,0,  2, 3)   // (6,7)
    CRYL(4,0,  8, 4)   // (1,2)
    CRYL(1,2,  0, 5)   // (3,4)
    CRYL(2,4,  0, 6)   // (5,6)
    u3_g<8,0>(re, im, lane, u3p + 0*12);
    u3_g<0,2>(re, im, lane, u3p + 1*12);
    u3_g<0,4>(re, im, lane, u3p + 2*12);
    u3_g<0,1>(re, im, lane, u3p + 3*12);
    CRYR(2,0,  8, 7)   // (1,3)
    CRYR(1,4,  0, 8)   // (5,7)
    CRYR(4,2,  0, 9)   // (3,5)
#undef CRYL
#undef CRYR
    u3_g<0,2>(re, im, lane, u3p + 4*12);
    u3_g<0,1>(re, im, lane, u3p + 5*12);
    measure(re, im, pm1, z3, z7);
}

// CRZ branch: diagonal layers via pre-packed tables: re' = pc.re + psn.im ; im' = pc.im + ps.re
__device__ __forceinline__ void run_branch_z(const u64 bre[8], const u64 bim[8], int lane,
        const u64* Apc, const u64* Aps, const u64* Apsn,
        const u64* Bpc, const u64* Bps, const u64* Bpsn,
        const u64* u3p, u64 pm1, u64& z3, u64& z7){
    u64 re[8], im[8];
#pragma unroll
    for (int j = 0; j < 8; j++){
        int idx = j*32 + lane;
        re[j] = pfma(Apc[idx], bre[j], pmul(Apsn[idx], bim[j]));
        im[j] = pfma(Apc[idx], bim[j], pmul(Aps[idx],  bre[j]));
    }
    u3_g<8,0>(re, im, lane, u3p + 0*12);
    u3_g<0,2>(re, im, lane, u3p + 1*12);
    u3_g<0,4>(re, im, lane, u3p + 2*12);
    u3_g<0,1>(re, im, lane, u3p + 3*12);
#pragma unroll
    for (int j = 0; j < 8; j++){
        int idx = j*32 + lane;
        u64 r = pfma(Bpc[idx], re[j], pmul(Bpsn[idx], im[j]));
        im[j] = pfma(Bpc[idx], im[j], pmul(Bps[idx],  re[j]));
        re[j] = r;
    }
    u3_g<0,2>(re, im, lane, u3p + 4*12);
    u3_g<0,1>(re, im, lane, u3p + 5*12);
    measure(re, im, pm1, z3, z7);
}

__global__ void __launch_bounds__(128, 5)
qcnn_kernel(const float* __restrict__ theta, const float* __restrict__ phi,
            const float* __restrict__ crw, const float* __restrict__ u3p,
            const float* __restrict__ W1, const float* __restrict__ b1,
            const float* __restrict__ W2, const float* __restrict__ b2,
            float* __restrict__ out, int n)
{
    __shared__ float s_crc[10], s_crs[10];
    __shared__ u64 s_u3p[18*12];          // pre-packed broadcast U3 coefficients
    __shared__ float s_W1[72], s_b1[12], s_W2[12], s_b2;
    __shared__ u64 s_Apc[256], s_Aps[256], s_Apsn[256];
    __shared__ u64 s_Bpc[256], s_Bps[256], s_Bpsn[256];

    int tid = threadIdx.x;
    if (tid < 72)                         s_W1[tid]     = W1[tid];
    else if (tid < 84)                    s_b1[tid-72]  = b1[tid-72];
    else if (tid < 96)                    s_W2[tid-84]  = W2[tid-84];
    else if (tid == 96)                   s_b2          = b2[0];
    else if (tid >= 98 && tid < 108){
        int i = tid - 98;
        float t = 0.5f * crw[i];
        s_crc[i] = cosf(t);
        s_crs[i] = sinf(t);
    } else if (tid >= 108 && tid < 126){
        int g = tid - 108;   // branch*6 + gate
        float t  = u3p[g*3+0], ph = u3p[g*3+1], la = u3p[g*3+2];
        float ct, stt; sincosf(0.5f*t, &stt, &ct);
        float cl, sl;  sincosf(la,     &sl,  &cl);
        float cp, sp;  sincosf(ph,     &sp,  &cp);
        float m01x = -cl*stt, m01y = -sl*stt;
        float m10x =  cp*stt, m10y =  sp*stt;
        float m11x = (cp*cl - sp*sl)*ct, m11y = (cp*sl + sp*cl)*ct;
        u64* q = s_u3p + g*12;
        q[0]  = pk(ct, ct);   q[1] = 0ull;           q[2] = 0ull;
        q[3]  = pk(m01x,m01x); q[4] = pk(m01y,m01y); q[5] = pk(-m01y,-m01y);
        q[6]  = pk(m11x,m11x); q[7] = pk(m11y,m11y); q[8] = pk(-m11y,-m11y);
        q[9]  = pk(m10x,m10x); q[10]= pk(m10y,m10y); q[11]= pk(-m10y,-m10y);
    }
    __syncthreads();

    // CRZ phase tables (pre-packed). Wire w bit of a = (a >> (7-w)) & 1.
    // Post-remap: lane = w0<<4|w1<<3|w2<<2|w6<<1|w4 ; j = w5<<2|w3<<1|w7
#pragma unroll
    for (int a = tid; a < 256; a += 128){
        C2 pA{1.f, 0.f}, pB{1.f, 0.f};
#define CRZF(P, cw, tw, i) \
        if ((a >> (7-(cw))) & 1){ \
            float ss = ((a >> (7-(tw))) & 1) ? s_crs[i] : -s_crs[i]; \
            P = cmul(P, C2{s_crc[i], ss}); \
        }
        CRZF(pA, 0,1, 0) CRZF(pA, 2,3, 1) CRZF(pA, 4,5, 2) CRZF(pA, 6,7, 3)
        CRZF(pA, 1,2, 4) CRZF(pA, 3,4, 5) CRZF(pA, 5,6, 6)
        CRZF(pB, 1,3, 7) CRZF(pB, 5,7, 8) CRZF(pB, 3,5, 9)
#undef CRZF
        int w0=(a>>7)&1, w1=(a>>6)&1, w2=(a>>5)&1, w3=(a>>4)&1;
        int w4=(a>>3)&1, w5=(a>>2)&1, w6=(a>>1)&1, w7=a&1;
        int idx = ((w5<<2)|(w3<<1)|w7)*32 + ((w0<<4)|(w1<<3)|(w2<<2)|(w6<<1)|w4);
        s_Apc[idx]  = pk(pA.x, pA.x);
        s_Aps[idx]  = pk(pA.y, pA.y);
        s_Apsn[idx] = pk(-pA.y, -pA.y);
        s_Bpc[idx]  = pk(pB.x, pB.x);
        s_Bps[idx]  = pk(pB.y, pB.y);
        s_Bpsn[idx] = pk(-pB.y, -pB.y);
    }
    __syncthreads();

    int lane = tid & 31;
    int wid = tid >> 5;
    int s2 = blockIdx.x * 8 + wid * 2;    // this warp handles samples s2, s2+1
    if (s2 >= n) return;
    int s2b = (s2 + 1 < n) ? s2 + 1 : s2;

    u64 pm1 = pk(-1.f, -1.f);

    float th0 = theta[s2], th1 = theta[s2b];
    float fi0 = phi[s2],   fi1 = phi[s2b];
    float c0, s0, c1, s1;
    __sincosf(th0, &s0, &c0);
    __sincosf(th1, &s1, &c1);
    u64 vrc = pk(c0, c1), vrs = pk(s0, s1), vrsn = pk(-s0, -s1);

    // RZ layer = diag phase e^{i*phi*(2*popc(a)-8)}; per-sample chains, packed per plane
    int pcl = __popc(lane);
    C2 wkA[4], wkB[4];
    {
        C2 zA, zB;
        __sincosf(2.f*fi0, &zA.y, &zA.x);
        __sincosf(2.f*fi1, &zB.y, &zB.x);
        __sincosf(2.f*fi0*(float)(pcl - 4), &wkA[0].y, &wkA[0].x);
        __sincosf(2.f*fi1*(float)(pcl - 4), &wkB[0].y, &wkB[0].x);
        wkA[1] = cmul(wkA[0], zA); wkA[2] = cmul(wkA[1], zA); wkA[3] = cmul(wkA[2], zA);
        wkB[1] = cmul(wkB[0], zB); wkB[2] = cmul(wkB[1], zB); wkB[3] = cmul(wkB[2], zB);
    }
    u64 wkre[4], wkim[4], wkimn[4];
#pragma unroll
    for (int k = 0; k < 4; k++){
        wkre[k]  = pk(wkA[k].x, wkB[k].x);
        wkim[k]  = pk(wkA[k].y, wkB[k].y);
        wkimn[k] = pk(-wkA[k].y, -wkB[k].y);
    }

    u64 re[8], im[8];
#pragma unroll
    for (int j = 0; j < 8; j++){ re[j] = pk(0.0625f, 0.0625f); im[j] = 0ull; }

    const int pcj[8] = {0,1,1,2,1,2,2,3};
#pragma unroll 1
    for (int cyc = 0; cyc < 4; cyc++){
#pragma unroll
        for (int j = 0; j < 8; j++){
            int k = pcj[j];
            u64 r0 = re[j];
            re[j] = pfma(wkre[k], r0, pmul(wkimn[k], im[j]));
            im[j] = pfma(wkre[k], im[j], pmul(wkim[k], r0));
        }
        // Loop map: w0:16 w1:8 w2:4 w3:2 w4:1 | w5:4 w6:2 w7:1
        crx_g<24,0,0>(re, im, re, im, vrc, vrs, vrsn);  // (0,1)
        crx_g< 6,0,0>(re, im, re, im, vrc, vrs, vrsn);  // (2,3)
        crx_g< 1,4,0>(re, im, re, im, vrc, vrs, vrsn);  // (4,5)
        crx_g< 0,3,0>(re, im, re, im, vrc, vrs, vrsn);  // (6,7)
        crx_g<12,0,0>(re, im, re, im, vrc, vrs, vrsn);  // (1,2)
        crx_g< 3,0,0>(re, im, re, im, vrc, vrs, vrsn);  // (3,4)
        crx_g< 0,6,0>(re, im, re, im, vrc, vrs, vrsn);  // (5,6)
    }

    // Remap: swap wire 3 (lane bit 2) <-> wire 6 (reg bit 2), both planes.
#pragma unroll
    for (int j0i = 0; j0i < 4; j0i++){
        const int j0 = (j0i & 1) | ((j0i & 2) << 1);  // {0,1,4,5}
        const int jh = j0 | 2;
        bool hi = (lane & 2) != 0;
        u64 sr = hi ? re[j0] : re[jh];
        u64 si = hi ? im[j0] : im[jh];
        sr = shfl64(sr, 2); si = shfl64(si, 2);
        if (hi){ re[j0] = sr; im[j0] = si; }
        else   { re[jh] = sr; im[jh] = si; }
    }

    u64 featp[6];
    run_branch_x(re, im, lane, s_crc, s_crs, s_u3p + 0,    pm1, featp[0], featp[1]);
    run_branch_y(re, im, lane, s_crc, s_crs, s_u3p + 6*12, pm1, featp[2], featp[3]);
    run_branch_z(re, im, lane, s_Apc, s_Aps, s_Apsn, s_Bpc, s_Bps, s_Bpsn,
                 s_u3p + 12*12, pm1, featp[4], featp[5]);

    if (lane < 2){
        int s = s2 + lane;
        if (s < n){
            float f[6];
#pragma unroll
            for (int i = 0; i < 6; i++){
                float lo, hi; upk(featp[i], lo, hi);
                f[i] = lane ? hi : lo;
            }
            float acc = s_b2;
#pragma unroll
            for (int k = 0; k < 12; k++){
                float u = s_b1[k];
#pragma unroll
                for (int i = 0; i < 6; i++) u += s_W1[k*6+i] * f[i];
                float e = __expf(2.f*u);                 // tanh via exp
                acc += s_W2[k] * (1.f - __fdividef(2.f, e + 1.f));
            }
            out[s] = __fdividef(1.f, 1.f + __expf(-acc));
        }
    }
}

extern "C" void kernel_launch(void* const* d_in, const int* in_sizes, int n_in,
                              void* d_out, int out_size)
{
    const float* theta = (const float*)d_in[0];
    const float* phi   = (const float*)d_in[1];
    const float* crw   = (const float*)d_in[2];
    const float* u3p   = (const float*)d_in[3];
    const float* W1    = (const float*)d_in[4];
    const float* b1    = (const float*)d_in[5];
    const float* W2    = (const float*)d_in[6];
    const float* b2    = (const float*)d_in[7];
    float* out = (float*)d_out;
    int n = in_sizes[0];
    int blocks = (n + 7) / 8;   // 4 warps/block, 2 samples/warp
    qcnn_kernel<<<blocks, 128>>>(theta, phi, crw, u3p, W1, b1, W2, b2, out, n);
}